// round 9
// baseline (speedup 1.0000x reference)
#include <cuda_runtime.h>
#include <cuda_fp16.h>

#define H 512
#define W 512
#define OW 128
#define OH 8
#define NPK 66            // even packs per row: halo cols 0..131
#define NT 256

#define CEH(a, b) { __half2 _t = __hmin2(a, b); (b) = __hmax2(a, b); (a) = _t; }

__device__ __forceinline__ int reflect_idx(int i) {
    i = abs(i);
    return (i >= H) ? (2 * H - 2 - i) : i;
}

// optimal 5-sort, 9 CE (elementwise on half2 lanes)
__device__ __forceinline__ void sort5h(__half2& x0, __half2& x1, __half2& x2,
                                       __half2& x3, __half2& x4) {
    CEH(x0, x1); CEH(x3, x4); CEH(x2, x4); CEH(x2, x3); CEH(x0, x3);
    CEH(x0, x2); CEH(x1, x4); CEH(x1, x3); CEH(x1, x2);
}

__device__ __forceinline__ __half2 u2h(unsigned u) { return *reinterpret_cast<__half2*>(&u); }
__device__ __forceinline__ unsigned h2u(__half2 h) { return *reinterpret_cast<unsigned*>(&h); }

// row statistics (validated R7-R8): window w0..w4 per half2 lane
__device__ __forceinline__ void top2h(__half2 w0, __half2 w1, __half2 w2, __half2 w3,
                                      __half2 w4, __half2& A, __half2& B) {
    __half2 a = __hmin2(w0, w1), b = __hmax2(w0, w1);
    __half2 c = __hmin2(w2, w3), d = __hmax2(w2, w3);
    __half2 e = __hmax2(a, c);
    __half2 f = __hmin2(b, d), g = __hmax2(b, d);
    B = __hmax2(g, w4);
    __half2 h = __hmin2(g, w4);
    A = __hmax2(__hmax2(f, e), h);
}
__device__ __forceinline__ void top3h(__half2 w0, __half2 w1, __half2 w2, __half2 w3,
                                      __half2 w4, __half2& C, __half2& D, __half2& E) {
    __half2 a = __hmin2(w0, w1), b = __hmax2(w0, w1);
    __half2 c = __hmin2(w2, w3), d = __hmax2(w2, w3);
    __half2 e = __hmax2(a, c);
    __half2 f = __hmin2(b, d), g = __hmax2(b, d);
    __half2 p = __hmin2(e, f), q = __hmax2(e, f);
    E = __hmax2(g, w4);
    __half2 u = __hmin2(g, w4);
    D = __hmax2(q, u);
    __half2 v = __hmin2(q, u);
    C = __hmax2(p, v);
}
__device__ __forceinline__ void mid3h(__half2 x0, __half2 x1, __half2 x2, __half2 x3,
                                      __half2 x4, __half2& F, __half2& G, __half2& Hh) {
    CEH(x0, x1); CEH(x2, x3); CEH(x0, x2);
    x4 = __hmax2(x0, x4);
    CEH(x1, x4);
    x3 = __hmin2(x3, x4);
    CEH(x1, x2); CEH(x2, x3); CEH(x1, x2);
    F = x1; G = x2; Hh = x3;
}
__device__ __forceinline__ void bot3h(__half2 w0, __half2 w1, __half2 w2, __half2 w3,
                                      __half2 w4, __half2& I, __half2& J, __half2& K) {
    __half2 a = __hmin2(w0, w1), b = __hmax2(w0, w1);
    __half2 c = __hmin2(w2, w3), d = __hmax2(w2, w3);
    __half2 e = __hmin2(b, d);
    __half2 f = __hmin2(a, c), g = __hmax2(a, c);
    __half2 p = __hmin2(g, e), q = __hmax2(g, e);
    I = __hmin2(f, w4);
    __half2 u = __hmax2(f, w4);
    J = __hmin2(p, u);
    __half2 v = __hmax2(p, u);
    K = __hmin2(q, v);
}
__device__ __forceinline__ void bot2h(__half2 w0, __half2 w1, __half2 w2, __half2 w3,
                                      __half2 w4, __half2& L, __half2& M) {
    __half2 a = __hmin2(w0, w1), b = __hmax2(w0, w1);
    __half2 c = __hmin2(w2, w3), d = __hmax2(w2, w3);
    __half2 e = __hmin2(b, d);
    __half2 f = __hmin2(a, c), g = __hmax2(a, c);
    L = __hmin2(f, w4);
    __half2 h = __hmax2(f, w4);
    M = __hmin2(__hmin2(g, e), h);
}

// median (7th smallest) of 13 staircase candidates (validated R4-R8).
__device__ __forceinline__ __half2 sel13h(__half2 A, __half2 B, __half2 C, __half2 D,
                                          __half2 E, __half2 F, __half2 G, __half2 Hh,
                                          __half2 I, __half2 J, __half2 K, __half2 L,
                                          __half2 M) {
    CEH(A, C); CEH(E, Hh); CEH(C, E); CEH(B, D); CEH(B, C); CEH(D, E);
    CEH(F, I); CEH(K, M); CEH(I, K); CEH(G, J); CEH(G, I); CEH(J, K);
    __half2 s5 = __hmax2(__hmax2(__hmax2(__hmin2(A, M), __hmin2(B, K)),
                                 __hmax2(__hmin2(C, J), __hmin2(D, I))),
                         __hmax2(__hmin2(E, G), __hmin2(Hh, F)));
    __half2 s6 = __hmax2(__hmax2(__hmax2(A, __hmin2(B, M)),
                                 __hmax2(__hmin2(C, K), __hmin2(D, J))),
                         __hmax2(__hmax2(__hmin2(E, I), __hmin2(Hh, G)), F));
    return __hmin2(__hmax2(s5, L), s6);
}

__global__ __launch_bounds__(NT, 6) void median5x5_h4b_kernel(
    const float* __restrict__ in, float* __restrict__ out) {
    // sorted even column-packs: pack p holds halo columns (2p, 2p+1) as half2
    __shared__ unsigned scolp[OH][5][NPK];

    const int bx = blockIdx.x * OW;
    const int by = blockIdx.y * OH;
    const int plane = blockIdx.z;
    const float* src = in + (size_t)plane * (H * W);

    const int tid = threadIdx.x;
    const bool interior = (bx >= 2) & (bx + OW + 2 <= W) & (by >= 2) & (by + OH + 2 <= H);

    // Phase B: sort each even column-pack over 5 vertically-adjacent rows.
    for (int k = tid; k < NPK * OH; k += NT) {
        int oy = k / NPK;
        int pp = k - oy * NPK;
        int sp = pp * 2;                        // even halo column
        __half2 v0, v1, v2, v3, v4;
        if (interior) {
            const float* p = src + (by + oy - 2) * W + (bx + sp - 2);   // 8B aligned
            v0 = __float22half2_rn(*(const float2*)(p));
            v1 = __float22half2_rn(*(const float2*)(p + W));
            v2 = __float22half2_rn(*(const float2*)(p + 2 * W));
            v3 = __float22half2_rn(*(const float2*)(p + 3 * W));
            v4 = __float22half2_rn(*(const float2*)(p + 4 * W));
        } else {
            int gx0 = reflect_idx(bx + sp - 2);
            int gx1 = reflect_idx(bx + sp - 1);
            int g0 = reflect_idx(by + oy - 2) * W;
            int g1 = reflect_idx(by + oy - 1) * W;
            int g2 = reflect_idx(by + oy + 0) * W;
            int g3 = reflect_idx(by + oy + 1) * W;
            int g4 = reflect_idx(by + oy + 2) * W;
            v0 = __floats2half2_rn(src[g0 + gx0], src[g0 + gx1]);
            v1 = __floats2half2_rn(src[g1 + gx0], src[g1 + gx1]);
            v2 = __floats2half2_rn(src[g2 + gx0], src[g2 + gx1]);
            v3 = __floats2half2_rn(src[g3 + gx0], src[g3 + gx1]);
            v4 = __floats2half2_rn(src[g4 + gx0], src[g4 + gx1]);
        }
        sort5h(v0, v1, v2, v3, v4);
        scolp[oy][0][pp] = h2u(v0);
        scolp[oy][1][pp] = h2u(v1);
        scolp[oy][2][pp] = h2u(v2);
        scolp[oy][3][pp] = h2u(v3);
        scolp[oy][4][pp] = h2u(v4);
    }
    __syncthreads();

    // Phase C: 4 pixels per thread = two independent half2 pairs at
    // NON-ADJACENT pack bases xp and xp+32 -> all LDS are lane-stride-1
    // (conflict-free), unlike R8's stride-2 layout.
    const int oy = tid >> 5;
    const int xp = tid & 31;

#define ROWPACKS(base, r, w0, w1, w2, w3, w4)                         \
    __half2 w0, w1, w2, w3, w4;                                       \
    {   unsigned _e0 = scolp[oy][r][(base) + 0];                      \
        unsigned _e1 = scolp[oy][r][(base) + 1];                      \
        unsigned _e2 = scolp[oy][r][(base) + 2];                      \
        w0 = u2h(_e0); w2 = u2h(_e1); w4 = u2h(_e2);                  \
        w1 = u2h(__byte_perm(_e0, _e1, 0x5432));                      \
        w3 = u2h(__byte_perm(_e1, _e2, 0x5432)); }

    __half2 A0, B0, C0, D0, E0, F0, G0, H0, I0, J0, K0, L0, M0;
    __half2 A1, B1, C1, D1, E1, F1, G1, H1, I1, J1, K1, L1, M1;

    {   ROWPACKS(xp, 0, a0, a1, a2, a3, a4);
        ROWPACKS(xp + 32, 0, b0, b1, b2, b3, b4);
        top2h(a0, a1, a2, a3, a4, A0, B0);
        top2h(b0, b1, b2, b3, b4, A1, B1);
    }
    {   ROWPACKS(xp, 1, a0, a1, a2, a3, a4);
        ROWPACKS(xp + 32, 1, b0, b1, b2, b3, b4);
        top3h(a0, a1, a2, a3, a4, C0, D0, E0);
        top3h(b0, b1, b2, b3, b4, C1, D1, E1);
    }
    {   ROWPACKS(xp, 2, a0, a1, a2, a3, a4);
        ROWPACKS(xp + 32, 2, b0, b1, b2, b3, b4);
        mid3h(a0, a1, a2, a3, a4, F0, G0, H0);
        mid3h(b0, b1, b2, b3, b4, F1, G1, H1);
    }
    {   ROWPACKS(xp, 3, a0, a1, a2, a3, a4);
        ROWPACKS(xp + 32, 3, b0, b1, b2, b3, b4);
        bot3h(a0, a1, a2, a3, a4, I0, J0, K0);
        bot3h(b0, b1, b2, b3, b4, I1, J1, K1);
    }
    {   ROWPACKS(xp, 4, a0, a1, a2, a3, a4);
        ROWPACKS(xp + 32, 4, b0, b1, b2, b3, b4);
        bot2h(a0, a1, a2, a3, a4, L0, M0);
        bot2h(b0, b1, b2, b3, b4, L1, M1);
    }

    __half2 med0 = sel13h(A0, B0, C0, D0, E0, F0, G0, H0, I0, J0, K0, L0, M0);
    __half2 med1 = sel13h(A1, B1, C1, D1, E1, F1, G1, H1, I1, J1, K1, L1, M1);

    float* orow = out + (size_t)plane * (H * W) + (by + oy) * W + bx;
    float2 o0; o0.x = __low2float(med0); o0.y = __high2float(med0);
    float2 o1; o1.x = __low2float(med1); o1.y = __high2float(med1);
    *(float2*)(orow + 2 * xp)      = o0;
    *(float2*)(orow + 64 + 2 * xp) = o1;
#undef ROWPACKS
}

extern "C" void kernel_launch(void* const* d_in, const int* in_sizes, int n_in,
                              void* d_out, int out_size) {
    const float* img = (const float*)d_in[0];
    float* out = (float*)d_out;
    int planes = in_sizes[0] / (H * W);   // 4 * 3 = 12

    dim3 block(NT);
    dim3 grid(W / OW, H / OH, planes);
    median5x5_h4b_kernel<<<grid, block>>>(img, out);
}

// round 10
// speedup vs baseline: 1.4865x; 1.4865x over previous
#include <cuda_runtime.h>
#include <cuda_fp16.h>

#define H 512
#define W 512
#define OW 128
#define OH 8
#define NPK 66            // packs per row: halo cols 0..131, pack p = cols (2p, 2p+1)
#define NT 256

// parity-split sorted-column storage:
//   even pack 2q  -> scol[IDXE(oy,r,q)]
//   odd  pack 2q+1-> scol[ODD + IDXE(oy,r,q)]
// ODD = 1328 = 8*5*33 + 8 pad; 1328 % 32 == 16 so even/odd halves of one STS
// hit disjoint bank sets.
#define EWORDS 1320       // 8*5*33
#define ODD    1328
#define IDXE(oy, r, q) (((oy) * 5 + (r)) * 33 + (q))

#define CEH(a, b) { __half2 _t = __hmin2(a, b); (b) = __hmax2(a, b); (a) = _t; }

__device__ __forceinline__ int reflect_idx(int i) {
    i = abs(i);
    return (i >= H) ? (2 * H - 2 - i) : i;
}

// optimal 5-sort, 9 CE (elementwise on half2 lanes)
__device__ __forceinline__ void sort5h(__half2& x0, __half2& x1, __half2& x2,
                                       __half2& x3, __half2& x4) {
    CEH(x0, x1); CEH(x3, x4); CEH(x2, x4); CEH(x2, x3); CEH(x0, x3);
    CEH(x0, x2); CEH(x1, x4); CEH(x1, x3); CEH(x1, x2);
}

__device__ __forceinline__ __half2 u2h(unsigned u) { return *reinterpret_cast<__half2*>(&u); }
__device__ __forceinline__ unsigned h2u(__half2 h) { return *reinterpret_cast<unsigned*>(&h); }

// row statistics (validated R7-R8): window w0..w4 per half2 lane
__device__ __forceinline__ void top2h(__half2 w0, __half2 w1, __half2 w2, __half2 w3,
                                      __half2 w4, __half2& A, __half2& B) {
    __half2 a = __hmin2(w0, w1), b = __hmax2(w0, w1);
    __half2 c = __hmin2(w2, w3), d = __hmax2(w2, w3);
    __half2 e = __hmax2(a, c);
    __half2 f = __hmin2(b, d), g = __hmax2(b, d);
    B = __hmax2(g, w4);
    __half2 h = __hmin2(g, w4);
    A = __hmax2(__hmax2(f, e), h);
}
__device__ __forceinline__ void top3h(__half2 w0, __half2 w1, __half2 w2, __half2 w3,
                                      __half2 w4, __half2& C, __half2& D, __half2& E) {
    __half2 a = __hmin2(w0, w1), b = __hmax2(w0, w1);
    __half2 c = __hmin2(w2, w3), d = __hmax2(w2, w3);
    __half2 e = __hmax2(a, c);
    __half2 f = __hmin2(b, d), g = __hmax2(b, d);
    __half2 p = __hmin2(e, f), q = __hmax2(e, f);
    E = __hmax2(g, w4);
    __half2 u = __hmin2(g, w4);
    D = __hmax2(q, u);
    __half2 v = __hmin2(q, u);
    C = __hmax2(p, v);
}
__device__ __forceinline__ void mid3h(__half2 x0, __half2 x1, __half2 x2, __half2 x3,
                                      __half2 x4, __half2& F, __half2& G, __half2& Hh) {
    CEH(x0, x1); CEH(x2, x3); CEH(x0, x2);
    x4 = __hmax2(x0, x4);
    CEH(x1, x4);
    x3 = __hmin2(x3, x4);
    CEH(x1, x2); CEH(x2, x3); CEH(x1, x2);
    F = x1; G = x2; Hh = x3;
}
__device__ __forceinline__ void bot3h(__half2 w0, __half2 w1, __half2 w2, __half2 w3,
                                      __half2 w4, __half2& I, __half2& J, __half2& K) {
    __half2 a = __hmin2(w0, w1), b = __hmax2(w0, w1);
    __half2 c = __hmin2(w2, w3), d = __hmax2(w2, w3);
    __half2 e = __hmin2(b, d);
    __half2 f = __hmin2(a, c), g = __hmax2(a, c);
    __half2 p = __hmin2(g, e), q = __hmax2(g, e);
    I = __hmin2(f, w4);
    __half2 u = __hmax2(f, w4);
    J = __hmin2(p, u);
    __half2 v = __hmax2(p, u);
    K = __hmin2(q, v);
}
__device__ __forceinline__ void bot2h(__half2 w0, __half2 w1, __half2 w2, __half2 w3,
                                      __half2 w4, __half2& L, __half2& M) {
    __half2 a = __hmin2(w0, w1), b = __hmax2(w0, w1);
    __half2 c = __hmin2(w2, w3), d = __hmax2(w2, w3);
    __half2 e = __hmin2(b, d);
    __half2 f = __hmin2(a, c), g = __hmax2(a, c);
    L = __hmin2(f, w4);
    __half2 h = __hmax2(f, w4);
    M = __hmin2(__hmin2(g, e), h);
}

// median (7th smallest) of 13 staircase candidates (validated R4-R9).
__device__ __forceinline__ __half2 sel13h(__half2 A, __half2 B, __half2 C, __half2 D,
                                          __half2 E, __half2 F, __half2 G, __half2 Hh,
                                          __half2 I, __half2 J, __half2 K, __half2 L,
                                          __half2 M) {
    CEH(A, C); CEH(E, Hh); CEH(C, E); CEH(B, D); CEH(B, C); CEH(D, E);
    CEH(F, I); CEH(K, M); CEH(I, K); CEH(G, J); CEH(G, I); CEH(J, K);
    __half2 s5 = __hmax2(__hmax2(__hmax2(__hmin2(A, M), __hmin2(B, K)),
                                 __hmax2(__hmin2(C, J), __hmin2(D, I))),
                         __hmax2(__hmin2(E, G), __hmin2(Hh, F)));
    __half2 s6 = __hmax2(__hmax2(__hmax2(A, __hmin2(B, M)),
                                 __hmax2(__hmin2(C, K), __hmin2(D, J))),
                         __hmax2(__hmax2(__hmin2(E, I), __hmin2(Hh, G)), F));
    return __hmin2(__hmax2(s5, L), s6);
}

__global__ __launch_bounds__(NT, 6) void median5x5_h4c_kernel(
    const float* __restrict__ in, float* __restrict__ out) {
    __shared__ unsigned scol[ODD + EWORDS];   // 2648 words = 10.6 KB

    const int bx = blockIdx.x * OW;
    const int by = blockIdx.y * OH;
    const int plane = blockIdx.z;
    const float* src = in + (size_t)plane * (H * W);

    const int tid = threadIdx.x;
    const int oy = tid >> 5;       // warp id == output row within block
    const int lane = tid & 31;
    const bool interior = (bx >= 2) & (bx + OW + 2 <= W) & (by >= 2) & (by + OH + 2 <= H);

    // Phase B: warp oy sorts row-oy's column packs; lanes stride packs.
    for (int p = lane; p < NPK; p += 32) {
        const int sp = p * 2;                   // even halo column
        __half2 v0, v1, v2, v3, v4;
        if (interior) {
            const float* ptr = src + (by + oy - 2) * W + (bx + sp - 2);   // 8B aligned
            v0 = __float22half2_rn(*(const float2*)(ptr));
            v1 = __float22half2_rn(*(const float2*)(ptr + W));
            v2 = __float22half2_rn(*(const float2*)(ptr + 2 * W));
            v3 = __float22half2_rn(*(const float2*)(ptr + 3 * W));
            v4 = __float22half2_rn(*(const float2*)(ptr + 4 * W));
        } else {
            int gx0 = reflect_idx(bx + sp - 2);
            int gx1 = reflect_idx(bx + sp - 1);
            int g0 = reflect_idx(by + oy - 2) * W;
            int g1 = reflect_idx(by + oy - 1) * W;
            int g2 = reflect_idx(by + oy + 0) * W;
            int g3 = reflect_idx(by + oy + 1) * W;
            int g4 = reflect_idx(by + oy + 2) * W;
            v0 = __floats2half2_rn(src[g0 + gx0], src[g0 + gx1]);
            v1 = __floats2half2_rn(src[g1 + gx0], src[g1 + gx1]);
            v2 = __floats2half2_rn(src[g2 + gx0], src[g2 + gx1]);
            v3 = __floats2half2_rn(src[g3 + gx0], src[g3 + gx1]);
            v4 = __floats2half2_rn(src[g4 + gx0], src[g4 + gx1]);
        }
        sort5h(v0, v1, v2, v3, v4);
        const int base = ((p & 1) ? ODD : 0) + IDXE(oy, 0, p >> 1);
        scol[base +   0] = h2u(v0);
        scol[base +  33] = h2u(v1);
        scol[base +  66] = h2u(v2);
        scol[base +  99] = h2u(v3);
        scol[base + 132] = h2u(v4);
    }
    __syncthreads();

    // Phase C: 4 adjacent pixels per thread = two independent half2 pairs,
    // sharing packed inputs (R8 structure) with conflict-free LDS:
    // packs 2xp -> E[xp], 2xp+1 -> O[xp], 2xp+2 -> E[xp+1], 2xp+3 -> O[xp+1].
    const int xp = lane;

#define ROWPACKS(r, w0, w1, w2, w3, w4, w5, w6)                       \
    __half2 w0, w1, w2, w3, w4, w5, w6;                               \
    {   unsigned _e0 = scol[IDXE(oy, r, xp)];                         \
        unsigned _e1 = scol[ODD + IDXE(oy, r, xp)];                   \
        unsigned _e2 = scol[IDXE(oy, r, xp + 1)];                     \
        unsigned _e3 = scol[ODD + IDXE(oy, r, xp + 1)];               \
        w0 = u2h(_e0); w2 = u2h(_e1); w4 = u2h(_e2); w6 = u2h(_e3);   \
        w1 = u2h(__byte_perm(_e0, _e1, 0x5432));                      \
        w3 = u2h(__byte_perm(_e1, _e2, 0x5432));                      \
        w5 = u2h(__byte_perm(_e2, _e3, 0x5432)); }

    __half2 A0, B0, C0, D0, E0, F0, G0, H0, I0, J0, K0, L0, M0;
    __half2 A1, B1, C1, D1, E1, F1, G1, H1, I1, J1, K1, L1, M1;

    {   ROWPACKS(0, w0, w1, w2, w3, w4, w5, w6);
        top2h(w0, w1, w2, w3, w4, A0, B0);
        top2h(w2, w3, w4, w5, w6, A1, B1);
    }
    {   ROWPACKS(1, w0, w1, w2, w3, w4, w5, w6);
        top3h(w0, w1, w2, w3, w4, C0, D0, E0);
        top3h(w2, w3, w4, w5, w6, C1, D1, E1);
    }
    {   ROWPACKS(2, w0, w1, w2, w3, w4, w5, w6);
        mid3h(w0, w1, w2, w3, w4, F0, G0, H0);
        mid3h(w2, w3, w4, w5, w6, F1, G1, H1);
    }
    {   ROWPACKS(3, w0, w1, w2, w3, w4, w5, w6);
        bot3h(w0, w1, w2, w3, w4, I0, J0, K0);
        bot3h(w2, w3, w4, w5, w6, I1, J1, K1);
    }
    {   ROWPACKS(4, w0, w1, w2, w3, w4, w5, w6);
        bot2h(w0, w1, w2, w3, w4, L0, M0);
        bot2h(w2, w3, w4, w5, w6, L1, M1);
    }

    __half2 med0 = sel13h(A0, B0, C0, D0, E0, F0, G0, H0, I0, J0, K0, L0, M0);
    __half2 med1 = sel13h(A1, B1, C1, D1, E1, F1, G1, H1, I1, J1, K1, L1, M1);

    float4 o;
    o.x = __low2float(med0);
    o.y = __high2float(med0);
    o.z = __low2float(med1);
    o.w = __high2float(med1);
    *(float4*)(out + (size_t)plane * (H * W) + (by + oy) * W + (bx + 4 * xp)) = o;
#undef ROWPACKS
}

extern "C" void kernel_launch(void* const* d_in, const int* in_sizes, int n_in,
                              void* d_out, int out_size) {
    const float* img = (const float*)d_in[0];
    float* out = (float*)d_out;
    int planes = in_sizes[0] / (H * W);   // 4 * 3 = 12

    dim3 block(NT);
    dim3 grid(W / OW, H / OH, planes);
    median5x5_h4c_kernel<<<grid, block>>>(img, out);
}

// round 11
// speedup vs baseline: 1.5976x; 1.0747x over previous
#include <cuda_runtime.h>
#include <cuda_fp16.h>

#define H 512
#define W 512
#define OW 128
#define OH 8
#define NPK 66            // even packs per row: halo cols 0..131
#define NT 256

#define CEH(a, b) { __half2 _t = __hmin2(a, b); (b) = __hmax2(a, b); (a) = _t; }

__device__ __forceinline__ int reflect_idx(int i) {
    i = abs(i);
    return (i >= H) ? (2 * H - 2 - i) : i;
}

// optimal 5-sort, 9 CE (elementwise on half2 lanes)
__device__ __forceinline__ void sort5h(__half2& x0, __half2& x1, __half2& x2,
                                       __half2& x3, __half2& x4) {
    CEH(x0, x1); CEH(x3, x4); CEH(x2, x4); CEH(x2, x3); CEH(x0, x3);
    CEH(x0, x2); CEH(x1, x4); CEH(x1, x3); CEH(x1, x2);
}

__device__ __forceinline__ __half2 u2h(unsigned u) { return *reinterpret_cast<__half2*>(&u); }
__device__ __forceinline__ unsigned h2u(__half2 h) { return *reinterpret_cast<unsigned*>(&h); }

// row statistics (validated R7-R10): window w0..w4 per half2 lane
__device__ __forceinline__ void top2h(__half2 w0, __half2 w1, __half2 w2, __half2 w3,
                                      __half2 w4, __half2& A, __half2& B) {
    __half2 a = __hmin2(w0, w1), b = __hmax2(w0, w1);
    __half2 c = __hmin2(w2, w3), d = __hmax2(w2, w3);
    __half2 e = __hmax2(a, c);
    __half2 f = __hmin2(b, d), g = __hmax2(b, d);
    B = __hmax2(g, w4);
    __half2 h = __hmin2(g, w4);
    A = __hmax2(__hmax2(f, e), h);
}
__device__ __forceinline__ void top3h(__half2 w0, __half2 w1, __half2 w2, __half2 w3,
                                      __half2 w4, __half2& C, __half2& D, __half2& E) {
    __half2 a = __hmin2(w0, w1), b = __hmax2(w0, w1);
    __half2 c = __hmin2(w2, w3), d = __hmax2(w2, w3);
    __half2 e = __hmax2(a, c);
    __half2 f = __hmin2(b, d), g = __hmax2(b, d);
    __half2 p = __hmin2(e, f), q = __hmax2(e, f);
    E = __hmax2(g, w4);
    __half2 u = __hmin2(g, w4);
    D = __hmax2(q, u);
    __half2 v = __hmin2(q, u);
    C = __hmax2(p, v);
}
__device__ __forceinline__ void mid3h(__half2 x0, __half2 x1, __half2 x2, __half2 x3,
                                      __half2 x4, __half2& F, __half2& G, __half2& Hh) {
    CEH(x0, x1); CEH(x2, x3); CEH(x0, x2);
    x4 = __hmax2(x0, x4);
    CEH(x1, x4);
    x3 = __hmin2(x3, x4);
    CEH(x1, x2); CEH(x2, x3); CEH(x1, x2);
    F = x1; G = x2; Hh = x3;
}
__device__ __forceinline__ void bot3h(__half2 w0, __half2 w1, __half2 w2, __half2 w3,
                                      __half2 w4, __half2& I, __half2& J, __half2& K) {
    __half2 a = __hmin2(w0, w1), b = __hmax2(w0, w1);
    __half2 c = __hmin2(w2, w3), d = __hmax2(w2, w3);
    __half2 e = __hmin2(b, d);
    __half2 f = __hmin2(a, c), g = __hmax2(a, c);
    __half2 p = __hmin2(g, e), q = __hmax2(g, e);
    I = __hmin2(f, w4);
    __half2 u = __hmax2(f, w4);
    J = __hmin2(p, u);
    __half2 v = __hmax2(p, u);
    K = __hmin2(q, v);
}
__device__ __forceinline__ void bot2h(__half2 w0, __half2 w1, __half2 w2, __half2 w3,
                                      __half2 w4, __half2& L, __half2& M) {
    __half2 a = __hmin2(w0, w1), b = __hmax2(w0, w1);
    __half2 c = __hmin2(w2, w3), d = __hmax2(w2, w3);
    __half2 e = __hmin2(b, d);
    __half2 f = __hmin2(a, c), g = __hmax2(a, c);
    L = __hmin2(f, w4);
    __half2 h = __hmax2(f, w4);
    M = __hmin2(__hmin2(g, e), h);
}

// median (7th smallest) of 13 staircase candidates (validated R4-R10).
__device__ __forceinline__ __half2 sel13h(__half2 A, __half2 B, __half2 C, __half2 D,
                                          __half2 E, __half2 F, __half2 G, __half2 Hh,
                                          __half2 I, __half2 J, __half2 K, __half2 L,
                                          __half2 M) {
    CEH(A, C); CEH(E, Hh); CEH(C, E); CEH(B, D); CEH(B, C); CEH(D, E);
    CEH(F, I); CEH(K, M); CEH(I, K); CEH(G, J); CEH(G, I); CEH(J, K);
    __half2 s5 = __hmax2(__hmax2(__hmax2(__hmin2(A, M), __hmin2(B, K)),
                                 __hmax2(__hmin2(C, J), __hmin2(D, I))),
                         __hmax2(__hmin2(E, G), __hmin2(Hh, F)));
    __half2 s6 = __hmax2(__hmax2(__hmax2(A, __hmin2(B, M)),
                                 __hmax2(__hmin2(C, K), __hmin2(D, J))),
                         __hmax2(__hmax2(__hmin2(E, I), __hmin2(Hh, G)), F));
    return __hmin2(__hmax2(s5, L), s6);
}

__global__ __launch_bounds__(NT, 6) void median5x5_h4w_kernel(
    const float* __restrict__ in, float* __restrict__ out) {
    // sorted even column-packs: pack p holds halo columns (2p, 2p+1) as half2
    __shared__ unsigned scolp[OH][5][NPK];

    const int bx = blockIdx.x * OW;
    const int by = blockIdx.y * OH;
    const int plane = blockIdx.z;
    const float* src = in + (size_t)plane * (H * W);

    const int tid = threadIdx.x;
    const int oy = tid >> 5;       // warp id == output row within block
    const int lane = tid & 31;
    const bool interior = (bx >= 2) & (bx + OW + 2 <= W) & (by >= 2) & (by + OH + 2 <= H);

    // Phase B (warp-private): warp oy sorts the column packs of ITS OWN row;
    // the only consumers are this warp's Phase C lanes -> no block barrier.
    for (int p = lane; p < NPK; p += 32) {
        const int sp = p * 2;                   // even halo column
        __half2 v0, v1, v2, v3, v4;
        if (interior) {
            const float* ptr = src + (by + oy - 2) * W + (bx + sp - 2);   // 8B aligned
            v0 = __float22half2_rn(*(const float2*)(ptr));
            v1 = __float22half2_rn(*(const float2*)(ptr + W));
            v2 = __float22half2_rn(*(const float2*)(ptr + 2 * W));
            v3 = __float22half2_rn(*(const float2*)(ptr + 3 * W));
            v4 = __float22half2_rn(*(const float2*)(ptr + 4 * W));
        } else {
            int gx0 = reflect_idx(bx + sp - 2);
            int gx1 = reflect_idx(bx + sp - 1);
            int g0 = reflect_idx(by + oy - 2) * W;
            int g1 = reflect_idx(by + oy - 1) * W;
            int g2 = reflect_idx(by + oy + 0) * W;
            int g3 = reflect_idx(by + oy + 1) * W;
            int g4 = reflect_idx(by + oy + 2) * W;
            v0 = __floats2half2_rn(src[g0 + gx0], src[g0 + gx1]);
            v1 = __floats2half2_rn(src[g1 + gx0], src[g1 + gx1]);
            v2 = __floats2half2_rn(src[g2 + gx0], src[g2 + gx1]);
            v3 = __floats2half2_rn(src[g3 + gx0], src[g3 + gx1]);
            v4 = __floats2half2_rn(src[g4 + gx0], src[g4 + gx1]);
        }
        sort5h(v0, v1, v2, v3, v4);
        scolp[oy][0][p] = h2u(v0);
        scolp[oy][1][p] = h2u(v1);
        scolp[oy][2][p] = h2u(v2);
        scolp[oy][3][p] = h2u(v3);
        scolp[oy][4][p] = h2u(v4);
    }
    __syncwarp();   // intra-warp visibility only; warps stay decoupled

    // Phase C (R8 structure): 4 adjacent pixels per thread = two independent
    // half2 pairs sharing packed inputs.
    const int xp = lane;
    const int pbase = 2 * xp;

#define ROWPACKS(r, w0, w1, w2, w3, w4, w5, w6)                       \
    __half2 w0, w1, w2, w3, w4, w5, w6;                               \
    {   unsigned _e0 = scolp[oy][r][pbase + 0];                       \
        unsigned _e1 = scolp[oy][r][pbase + 1];                       \
        unsigned _e2 = scolp[oy][r][pbase + 2];                       \
        unsigned _e3 = scolp[oy][r][pbase + 3];                       \
        w0 = u2h(_e0); w2 = u2h(_e1); w4 = u2h(_e2); w6 = u2h(_e3);   \
        w1 = u2h(__byte_perm(_e0, _e1, 0x5432));                      \
        w3 = u2h(__byte_perm(_e1, _e2, 0x5432));                      \
        w5 = u2h(__byte_perm(_e2, _e3, 0x5432)); }

    __half2 A0, B0, C0, D0, E0, F0, G0, H0, I0, J0, K0, L0, M0;
    __half2 A1, B1, C1, D1, E1, F1, G1, H1, I1, J1, K1, L1, M1;

    {   ROWPACKS(0, w0, w1, w2, w3, w4, w5, w6);
        top2h(w0, w1, w2, w3, w4, A0, B0);
        top2h(w2, w3, w4, w5, w6, A1, B1);
    }
    {   ROWPACKS(1, w0, w1, w2, w3, w4, w5, w6);
        top3h(w0, w1, w2, w3, w4, C0, D0, E0);
        top3h(w2, w3, w4, w5, w6, C1, D1, E1);
    }
    {   ROWPACKS(2, w0, w1, w2, w3, w4, w5, w6);
        mid3h(w0, w1, w2, w3, w4, F0, G0, H0);
        mid3h(w2, w3, w4, w5, w6, F1, G1, H1);
    }
    {   ROWPACKS(3, w0, w1, w2, w3, w4, w5, w6);
        bot3h(w0, w1, w2, w3, w4, I0, J0, K0);
        bot3h(w2, w3, w4, w5, w6, I1, J1, K1);
    }
    {   ROWPACKS(4, w0, w1, w2, w3, w4, w5, w6);
        bot2h(w0, w1, w2, w3, w4, L0, M0);
        bot2h(w2, w3, w4, w5, w6, L1, M1);
    }

    __half2 med0 = sel13h(A0, B0, C0, D0, E0, F0, G0, H0, I0, J0, K0, L0, M0);
    __half2 med1 = sel13h(A1, B1, C1, D1, E1, F1, G1, H1, I1, J1, K1, L1, M1);

    float4 o;
    o.x = __low2float(med0);
    o.y = __high2float(med0);
    o.z = __low2float(med1);
    o.w = __high2float(med1);
    *(float4*)(out + (size_t)plane * (H * W) + (by + oy) * W + (bx + 4 * xp)) = o;
#undef ROWPACKS
}

extern "C" void kernel_launch(void* const* d_in, const int* in_sizes, int n_in,
                              void* d_out, int out_size) {
    const float* img = (const float*)d_in[0];
    float* out = (float*)d_out;
    int planes = in_sizes[0] / (H * W);   // 4 * 3 = 12

    dim3 block(NT);
    dim3 grid(W / OW, H / OH, planes);
    median5x5_h4w_kernel<<<grid, block>>>(img, out);
}